// round 1
// baseline (speedup 1.0000x reference)
#include <cuda_runtime.h>
#include <cuda_bf16.h>
#include <cstdint>

typedef unsigned long long ull;

#define N_PTS 8192
#define DIM   128
#define EMB   16

// Scratch (device globals — no allocation allowed)
__device__ __align__(16) float g_z[N_PTS * EMB];
__device__ float g_sq[N_PTS];
__device__ float g_rowsum[N_PTS];

__device__ __forceinline__ float frcp(float x) {
    float r;
    asm("rcp.approx.ftz.f32 %0, %1;" : "=f"(r) : "f"(x));
    return r;
}

__device__ __forceinline__ void fma2(ull &d, ull a, ull b) {
    asm("fma.rn.f32x2 %0, %1, %2, %0;" : "+l"(d) : "l"(a), "l"(b));
}

__device__ __forceinline__ void unpack2(ull v, float &lo, float &hi) {
    asm("mov.b64 {%0, %1}, %2;" : "=f"(lo), "=f"(hi) : "l"(v));
}

// ---------------------------------------------------------------------------
// Kernel 1: encoder. One thread per row. Weights in shared.
// ---------------------------------------------------------------------------
__global__ __launch_bounds__(128) void encoder_kernel(
    const float* __restrict__ x,
    const float* __restrict__ W1, const float* __restrict__ b1,
    const float* __restrict__ W2, const float* __restrict__ b2,
    const float* __restrict__ W3, const float* __restrict__ b3,
    const float* __restrict__ W4, const float* __restrict__ b4)
{
    __shared__ __align__(16) float sW1[128 * 64];
    __shared__ __align__(16) float sW2[64 * 32];
    __shared__ __align__(16) float sW3[32 * 16];
    __shared__ __align__(16) float sW4[16 * 16];
    __shared__ float sb1[64], sb2[32], sb3[16], sb4[16];

    const int t = threadIdx.x;
    for (int i = t; i < 128 * 64; i += 128) sW1[i] = W1[i];
    for (int i = t; i < 64 * 32;  i += 128) sW2[i] = W2[i];
    for (int i = t; i < 32 * 16;  i += 128) sW3[i] = W3[i];
    for (int i = t; i < 16 * 16;  i += 128) sW4[i] = W4[i];
    if (t < 64) sb1[t] = b1[t];
    if (t < 32) sb2[t] = b2[t];
    if (t < 16) { sb3[t] = b3[t]; sb4[t] = b4[t]; }
    __syncthreads();

    const int row = blockIdx.x * 128 + t;
    const float* xr = x + (size_t)row * DIM;

    // layer 1: 128 -> 64
    float h1[64];
    #pragma unroll
    for (int j = 0; j < 64; j++) h1[j] = sb1[j];
    for (int k = 0; k < 128; k++) {
        const float xk = xr[k];
        const float4* wr = reinterpret_cast<const float4*>(&sW1[k * 64]);
        #pragma unroll
        for (int j4 = 0; j4 < 16; j4++) {
            float4 w = wr[j4];
            h1[j4 * 4 + 0] = fmaf(xk, w.x, h1[j4 * 4 + 0]);
            h1[j4 * 4 + 1] = fmaf(xk, w.y, h1[j4 * 4 + 1]);
            h1[j4 * 4 + 2] = fmaf(xk, w.z, h1[j4 * 4 + 2]);
            h1[j4 * 4 + 3] = fmaf(xk, w.w, h1[j4 * 4 + 3]);
        }
    }
    #pragma unroll
    for (int j = 0; j < 64; j++) h1[j] = fmaxf(h1[j], 0.0f);

    // layer 2: 64 -> 32
    float h2[32];
    #pragma unroll
    for (int j = 0; j < 32; j++) h2[j] = sb2[j];
    #pragma unroll 4
    for (int k = 0; k < 64; k++) {
        const float hk = h1[k];
        const float4* wr = reinterpret_cast<const float4*>(&sW2[k * 32]);
        #pragma unroll
        for (int j4 = 0; j4 < 8; j4++) {
            float4 w = wr[j4];
            h2[j4 * 4 + 0] = fmaf(hk, w.x, h2[j4 * 4 + 0]);
            h2[j4 * 4 + 1] = fmaf(hk, w.y, h2[j4 * 4 + 1]);
            h2[j4 * 4 + 2] = fmaf(hk, w.z, h2[j4 * 4 + 2]);
            h2[j4 * 4 + 3] = fmaf(hk, w.w, h2[j4 * 4 + 3]);
        }
    }
    #pragma unroll
    for (int j = 0; j < 32; j++) h2[j] = fmaxf(h2[j], 0.0f);

    // layer 3: 32 -> 16
    float h3[16];
    #pragma unroll
    for (int j = 0; j < 16; j++) h3[j] = sb3[j];
    #pragma unroll 4
    for (int k = 0; k < 32; k++) {
        const float hk = h2[k];
        const float4* wr = reinterpret_cast<const float4*>(&sW3[k * 16]);
        #pragma unroll
        for (int j4 = 0; j4 < 4; j4++) {
            float4 w = wr[j4];
            h3[j4 * 4 + 0] = fmaf(hk, w.x, h3[j4 * 4 + 0]);
            h3[j4 * 4 + 1] = fmaf(hk, w.y, h3[j4 * 4 + 1]);
            h3[j4 * 4 + 2] = fmaf(hk, w.z, h3[j4 * 4 + 2]);
            h3[j4 * 4 + 3] = fmaf(hk, w.w, h3[j4 * 4 + 3]);
        }
    }
    #pragma unroll
    for (int j = 0; j < 16; j++) h3[j] = fmaxf(h3[j], 0.0f);

    // layer 4: 16 -> 16 (no relu)
    float z[16];
    #pragma unroll
    for (int j = 0; j < 16; j++) z[j] = sb4[j];
    #pragma unroll
    for (int k = 0; k < 16; k++) {
        const float hk = h3[k];
        const float4* wr = reinterpret_cast<const float4*>(&sW4[k * 16]);
        #pragma unroll
        for (int j4 = 0; j4 < 4; j4++) {
            float4 w = wr[j4];
            z[j4 * 4 + 0] = fmaf(hk, w.x, z[j4 * 4 + 0]);
            z[j4 * 4 + 1] = fmaf(hk, w.y, z[j4 * 4 + 1]);
            z[j4 * 4 + 2] = fmaf(hk, w.z, z[j4 * 4 + 2]);
            z[j4 * 4 + 3] = fmaf(hk, w.w, z[j4 * 4 + 3]);
        }
    }

    float s = 0.0f;
    #pragma unroll
    for (int j = 0; j < 16; j++) s = fmaf(z[j], z[j], s);
    g_sq[row] = s;

    float4* zo = reinterpret_cast<float4*>(&g_z[(size_t)row * EMB]);
    zo[0] = make_float4(z[0], z[1], z[2], z[3]);
    zo[1] = make_float4(z[4], z[5], z[6], z[7]);
    zo[2] = make_float4(z[8], z[9], z[10], z[11]);
    zo[3] = make_float4(z[12], z[13], z[14], z[15]);
}

// ---------------------------------------------------------------------------
// Shared inner compute: 4x4 register tile, f32x2 packed dot over EMB=16.
// zis: [64][16] float (row i local). zjs: [8][64] ull (k2-major packed pairs).
// ---------------------------------------------------------------------------

// ---------------------------------------------------------------------------
// Kernel 2: row sums. Block = 64 rows, loops over all 8192 cols in 64-tiles.
// ---------------------------------------------------------------------------
__global__ __launch_bounds__(256) void rowsum_kernel()
{
    __shared__ __align__(16) float zis[64][16];
    __shared__ __align__(16) ull   zjs[8][64];
    __shared__ float sqis[64];
    __shared__ float sqjs[64];
    __shared__ float rs[64];

    const int t  = threadIdx.x;
    const int tx = t & 15;
    const int ty = t >> 4;
    const int i0 = blockIdx.x * 64;

    // load zi tile (once)
    {
        int row = t >> 2;           // 0..63
        int c4  = t & 3;            // 0..3
        const float4* src = reinterpret_cast<const float4*>(&g_z[(size_t)(i0 + row) * EMB + c4 * 4]);
        *reinterpret_cast<float4*>(&zis[row][c4 * 4]) = *src;
    }
    if (t < 64) { sqis[t] = g_sq[i0 + t]; rs[t] = 0.0f; }

    float s0 = 0.0f, s1 = 0.0f, s2 = 0.0f, s3 = 0.0f;

    for (int jt = 0; jt < N_PTS / 64; jt++) {
        const int j0 = jt * 64;
        __syncthreads();
        // load zj tile (k2-major packed)
        {
            #pragma unroll
            for (int r = 0; r < 2; r++) {
                int idx = t + r * 256;          // 0..511
                int k2  = idx >> 6;
                int j   = idx & 63;
                zjs[k2][j] = *reinterpret_cast<const ull*>(&g_z[(size_t)(j0 + j) * EMB + k2 * 2]);
            }
        }
        if (t < 64) sqjs[t] = g_sq[j0 + t];
        __syncthreads();

        ull acc[16];
        #pragma unroll
        for (int m = 0; m < 16; m++) acc[m] = 0ull;

        #pragma unroll
        for (int k2 = 0; k2 < 8; k2++) {
            ulonglong2 b01 = *reinterpret_cast<const ulonglong2*>(&zjs[k2][tx * 4]);
            ulonglong2 b23 = *reinterpret_cast<const ulonglong2*>(&zjs[k2][tx * 4 + 2]);
            ull a[4];
            #pragma unroll
            for (int ii = 0; ii < 4; ii++)
                a[ii] = *reinterpret_cast<const ull*>(&zis[ty * 4 + ii][k2 * 2]);
            #pragma unroll
            for (int ii = 0; ii < 4; ii++) {
                fma2(acc[ii * 4 + 0], a[ii], b01.x);
                fma2(acc[ii * 4 + 1], a[ii], b01.y);
                fma2(acc[ii * 4 + 2], a[ii], b23.x);
                fma2(acc[ii * 4 + 3], a[ii], b23.y);
            }
        }

        float partial[4];
        #pragma unroll
        for (int ii = 0; ii < 4; ii++) {
            const float si = sqis[ty * 4 + ii];
            float p = 0.0f;
            #pragma unroll
            for (int jj = 0; jj < 4; jj++) {
                float lo, hi;
                unpack2(acc[ii * 4 + jj], lo, hi);
                float dot = lo + hi;
                float dist = fmaxf(fmaf(-2.0f, dot, si + sqjs[tx * 4 + jj]), 0.0f);
                p += frcp(1.0f + dist);
            }
            partial[ii] = p;
        }
        s0 += partial[0]; s1 += partial[1]; s2 += partial[2]; s3 += partial[3];
    }

    __syncthreads();
    atomicAdd(&rs[ty * 4 + 0], s0);
    atomicAdd(&rs[ty * 4 + 1], s1);
    atomicAdd(&rs[ty * 4 + 2], s2);
    atomicAdd(&rs[ty * 4 + 3], s3);
    __syncthreads();
    if (t < 64) g_rowsum[i0 + t] = rs[t];
}

// ---------------------------------------------------------------------------
// Kernel 3: writer. One 64x64 tile per block; recompute + normalize + store.
// ---------------------------------------------------------------------------
__global__ __launch_bounds__(256) void writer_kernel(float* __restrict__ out)
{
    __shared__ __align__(16) float zis[64][16];
    __shared__ __align__(16) ull   zjs[8][64];
    __shared__ float sqis[64];
    __shared__ float sqjs[64];
    __shared__ float rinv[64];

    const int t  = threadIdx.x;
    const int tx = t & 15;
    const int ty = t >> 4;
    const int j0 = blockIdx.x * 64;
    const int i0 = blockIdx.y * 64;

    {
        int row = t >> 2;
        int c4  = t & 3;
        const float4* src = reinterpret_cast<const float4*>(&g_z[(size_t)(i0 + row) * EMB + c4 * 4]);
        *reinterpret_cast<float4*>(&zis[row][c4 * 4]) = *src;
    }
    {
        #pragma unroll
        for (int r = 0; r < 2; r++) {
            int idx = t + r * 256;
            int k2  = idx >> 6;
            int j   = idx & 63;
            zjs[k2][j] = *reinterpret_cast<const ull*>(&g_z[(size_t)(j0 + j) * EMB + k2 * 2]);
        }
    }
    if (t < 64) sqis[t] = g_sq[i0 + t];
    else if (t < 128) sqjs[t - 64] = g_sq[j0 + (t - 64)];
    else if (t < 192) rinv[t - 128] = frcp(g_rowsum[i0 + (t - 128)]);
    __syncthreads();

    ull acc[16];
    #pragma unroll
    for (int m = 0; m < 16; m++) acc[m] = 0ull;

    #pragma unroll
    for (int k2 = 0; k2 < 8; k2++) {
        ulonglong2 b01 = *reinterpret_cast<const ulonglong2*>(&zjs[k2][tx * 4]);
        ulonglong2 b23 = *reinterpret_cast<const ulonglong2*>(&zjs[k2][tx * 4 + 2]);
        ull a[4];
        #pragma unroll
        for (int ii = 0; ii < 4; ii++)
            a[ii] = *reinterpret_cast<const ull*>(&zis[ty * 4 + ii][k2 * 2]);
        #pragma unroll
        for (int ii = 0; ii < 4; ii++) {
            fma2(acc[ii * 4 + 0], a[ii], b01.x);
            fma2(acc[ii * 4 + 1], a[ii], b01.y);
            fma2(acc[ii * 4 + 2], a[ii], b23.x);
            fma2(acc[ii * 4 + 3], a[ii], b23.y);
        }
    }

    const float sj0 = sqjs[tx * 4 + 0];
    const float sj1 = sqjs[tx * 4 + 1];
    const float sj2 = sqjs[tx * 4 + 2];
    const float sj3 = sqjs[tx * 4 + 3];

    #pragma unroll
    for (int ii = 0; ii < 4; ii++) {
        const int i = i0 + ty * 4 + ii;
        const float si = sqis[ty * 4 + ii];
        const float rv = rinv[ty * 4 + ii];
        float lo, hi, dot, dist;
        float4 v;
        unpack2(acc[ii * 4 + 0], lo, hi); dot = lo + hi;
        dist = fmaxf(fmaf(-2.0f, dot, si + sj0), 0.0f);
        v.x = frcp(1.0f + dist) * rv;
        unpack2(acc[ii * 4 + 1], lo, hi); dot = lo + hi;
        dist = fmaxf(fmaf(-2.0f, dot, si + sj1), 0.0f);
        v.y = frcp(1.0f + dist) * rv;
        unpack2(acc[ii * 4 + 2], lo, hi); dot = lo + hi;
        dist = fmaxf(fmaf(-2.0f, dot, si + sj2), 0.0f);
        v.z = frcp(1.0f + dist) * rv;
        unpack2(acc[ii * 4 + 3], lo, hi); dot = lo + hi;
        dist = fmaxf(fmaf(-2.0f, dot, si + sj3), 0.0f);
        v.w = frcp(1.0f + dist) * rv;

        *reinterpret_cast<float4*>(&out[(size_t)i * N_PTS + j0 + tx * 4]) = v;
    }
}

// ---------------------------------------------------------------------------
extern "C" void kernel_launch(void* const* d_in, const int* in_sizes, int n_in,
                              void* d_out, int out_size)
{
    const float* x  = (const float*)d_in[0];
    const float* W1 = (const float*)d_in[1];
    const float* b1 = (const float*)d_in[2];
    const float* W2 = (const float*)d_in[3];
    const float* b2 = (const float*)d_in[4];
    const float* W3 = (const float*)d_in[5];
    const float* b3 = (const float*)d_in[6];
    const float* W4 = (const float*)d_in[7];
    const float* b4 = (const float*)d_in[8];
    float* out = (float*)d_out;

    encoder_kernel<<<N_PTS / 128, 128>>>(x, W1, b1, W2, b2, W3, b3, W4, b4);
    rowsum_kernel<<<N_PTS / 64, 256>>>();
    writer_kernel<<<dim3(N_PTS / 64, N_PTS / 64), 256>>>(out);
}

// round 2
// speedup vs baseline: 1.7009x; 1.7009x over previous
#include <cuda_runtime.h>
#include <cuda_bf16.h>
#include <cstdint>

typedef unsigned long long ull;

#define N_PTS 8192
#define DIM   128
#define EMB   16

// Scratch (device globals — no allocation allowed)
__device__ __align__(16) float g_z[N_PTS * EMB];
__device__ float g_sq[N_PTS];
__device__ float g_rowsum[N_PTS];

__device__ __forceinline__ float frcp(float x) {
    float r;
    asm("rcp.approx.ftz.f32 %0, %1;" : "=f"(r) : "f"(x));
    return r;
}
__device__ __forceinline__ void fma2(ull &d, ull a, ull b) {
    asm("fma.rn.f32x2 %0, %1, %2, %0;" : "+l"(d) : "l"(a), "l"(b));
}
__device__ __forceinline__ void unpack2(ull v, float &lo, float &hi) {
    asm("mov.b64 {%0, %1}, %2;" : "=f"(lo), "=f"(hi) : "l"(v));
}
__device__ __forceinline__ ull bcast2(float x) {
    ull v;
    asm("mov.b64 %0, {%1, %1};" : "=l"(v) : "f"(x));
    return v;
}

// b-tile 16B-chunk swizzle: logical j -> physical ull slot.
// chunk c = j>>1 (2 ulls... actually 2 j's = 16B); physical chunk = (c>>1) + 16*(c&1)
__device__ __forceinline__ int bswz(int j) {
    return 2 * ((j >> 2) + ((j >> 1) & 1) * 16) + (j & 1);
}

// ===========================================================================
// Encoder: 128 blocks x 256 threads, 64 rows/block, 4 threads per row.
// Dynamic shared memory (~95.5KB).
// ===========================================================================
#define ENC_SMEM 95744
#define OFF_W1   0          // ull[128*32]          32768 B
#define OFF_X    32768      // float[64][132]       33792 B
#define OFF_W2   66560      // float[64*32]          8192 B
#define OFF_W3   74752      // float[32*16]          2048 B
#define OFF_W4   76800      // float[16*16]          1024 B
#define OFF_B1   77824
#define OFF_B2   78080
#define OFF_B3   78208
#define OFF_B4   78272
#define OFF_EX   78336      // float[64][68]        17408 B

__global__ __launch_bounds__(256) void encoder_kernel(
    const float* __restrict__ x,
    const float* __restrict__ W1, const float* __restrict__ b1,
    const float* __restrict__ W2, const float* __restrict__ b2,
    const float* __restrict__ W3, const float* __restrict__ b3,
    const float* __restrict__ W4, const float* __restrict__ b4)
{
    extern __shared__ char dyn[];
    ull*   sW1 = (ull*)(dyn + OFF_W1);
    float* sx  = (float*)(dyn + OFF_X);
    float* sW2 = (float*)(dyn + OFF_W2);
    float* sW3 = (float*)(dyn + OFF_W3);
    float* sW4 = (float*)(dyn + OFF_W4);
    float* sb1 = (float*)(dyn + OFF_B1);
    float* sb2 = (float*)(dyn + OFF_B2);
    float* sb3 = (float*)(dyn + OFF_B3);
    float* sb4 = (float*)(dyn + OFF_B4);
    float* exch = (float*)(dyn + OFF_EX);

    const int t  = threadIdx.x;
    const int i0 = blockIdx.x * 64;

    // zero rowsum accumulators (used by rowsum kernel's atomics)
    int gid = blockIdx.x * 256 + t;
    if (gid < N_PTS) g_rowsum[gid] = 0.0f;

    // ---- cooperative staging (all coalesced) ----
    {
        const ulonglong2* src = (const ulonglong2*)W1;
        ulonglong2* dst = (ulonglong2*)sW1;
        #pragma unroll
        for (int r = 0; r < 8; r++) dst[t + r * 256] = src[t + r * 256];
    }
    {
        const float4* x4 = (const float4*)(x + (size_t)i0 * DIM);
        #pragma unroll
        for (int r = 0; r < 8; r++) {
            int idx = t + r * 256;
            int row = idx >> 5, c = idx & 31;
            *(float4*)&sx[row * 132 + c * 4] = x4[idx];
        }
    }
    {
        const float4* s = (const float4*)W2;
        float4* d = (float4*)sW2;
        d[t] = s[t]; d[t + 256] = s[t + 256];
    }
    if (t < 128) ((float4*)sW3)[t] = ((const float4*)W3)[t];
    if (t < 64)  ((float4*)sW4)[t] = ((const float4*)W4)[t];
    if (t < 64) sb1[t] = b1[t];
    if (t < 32) sb2[t] = b2[t];
    if (t < 16) sb3[t] = b3[t];
    if (t < 16) sb4[t] = b4[t];
    __syncthreads();

    const int r  = t >> 2;      // row within block (0..63)
    const int q4 = t & 3;       // quarter
    const float* xr = &sx[r * 132];
    float* exr = &exch[r * 68];

    // ---- layer 1: 128 -> 64 ; quarter computes 16 outputs (8 f32x2) ----
    ull acc1[8];
    #pragma unroll
    for (int p = 0; p < 8; p++) acc1[p] = ((const ull*)sb1)[q4 * 8 + p];
    #pragma unroll 2
    for (int k = 0; k < 128; k += 4) {
        float4 xv = *(const float4*)&xr[k];
        float xs[4] = {xv.x, xv.y, xv.z, xv.w};
        #pragma unroll
        for (int c = 0; c < 4; c++) {
            ull xx = bcast2(xs[c]);
            const ulonglong2* w = (const ulonglong2*)&sW1[(k + c) * 32 + q4 * 8];
            #pragma unroll
            for (int m = 0; m < 4; m++) {
                ulonglong2 wv = w[m];
                fma2(acc1[2 * m],     xx, wv.x);
                fma2(acc1[2 * m + 1], xx, wv.y);
            }
        }
    }
    #pragma unroll
    for (int p = 0; p < 8; p += 2) {
        float a, b_, c, d;
        unpack2(acc1[p], a, b_); unpack2(acc1[p + 1], c, d);
        *(float4*)&exr[q4 * 16 + p * 2] =
            make_float4(fmaxf(a, 0.f), fmaxf(b_, 0.f), fmaxf(c, 0.f), fmaxf(d, 0.f));
    }
    __syncthreads();

    // ---- layer 2: 64 -> 32 ; quarter computes 8 outputs (4 f32x2) ----
    float h1f[64];
    #pragma unroll
    for (int m = 0; m < 16; m++) *(float4*)&h1f[m * 4] = *(const float4*)&exr[m * 4];
    __syncthreads();

    ull acc2[4];
    #pragma unroll
    for (int p = 0; p < 4; p++) acc2[p] = ((const ull*)sb2)[q4 * 4 + p];
    #pragma unroll 4
    for (int k = 0; k < 64; k++) {
        ull hh = bcast2(h1f[k]);
        const ulonglong2* w = (const ulonglong2*)&((ull*)sW2)[k * 16 + q4 * 4];
        ulonglong2 w0 = w[0], w1 = w[1];
        fma2(acc2[0], hh, w0.x); fma2(acc2[1], hh, w0.y);
        fma2(acc2[2], hh, w1.x); fma2(acc2[3], hh, w1.y);
    }
    #pragma unroll
    for (int p = 0; p < 4; p += 2) {
        float a, b_, c, d;
        unpack2(acc2[p], a, b_); unpack2(acc2[p + 1], c, d);
        *(float4*)&exr[q4 * 8 + p * 2] =
            make_float4(fmaxf(a, 0.f), fmaxf(b_, 0.f), fmaxf(c, 0.f), fmaxf(d, 0.f));
    }
    __syncthreads();

    // ---- layer 3: 32 -> 16 ; quarter computes 4 outputs (2 f32x2) ----
    float h2f[32];
    #pragma unroll
    for (int m = 0; m < 8; m++) *(float4*)&h2f[m * 4] = *(const float4*)&exr[m * 4];
    __syncthreads();

    ull acc3[2];
    acc3[0] = ((const ull*)sb3)[q4 * 2];
    acc3[1] = ((const ull*)sb3)[q4 * 2 + 1];
    #pragma unroll
    for (int k = 0; k < 32; k++) {
        ull hh = bcast2(h2f[k]);
        ulonglong2 w = *(const ulonglong2*)&((ull*)sW3)[k * 8 + q4 * 2];
        fma2(acc3[0], hh, w.x); fma2(acc3[1], hh, w.y);
    }
    {
        float a, b_, c, d;
        unpack2(acc3[0], a, b_); unpack2(acc3[1], c, d);
        *(float4*)&exr[q4 * 4] =
            make_float4(fmaxf(a, 0.f), fmaxf(b_, 0.f), fmaxf(c, 0.f), fmaxf(d, 0.f));
    }
    __syncthreads();

    // ---- layer 4: 16 -> 16 (no relu); quarter computes 4 outputs ----
    float h3f[16];
    #pragma unroll
    for (int m = 0; m < 4; m++) *(float4*)&h3f[m * 4] = *(const float4*)&exr[m * 4];

    ull acc4[2];
    acc4[0] = ((const ull*)sb4)[q4 * 2];
    acc4[1] = ((const ull*)sb4)[q4 * 2 + 1];
    #pragma unroll
    for (int k = 0; k < 16; k++) {
        ull hh = bcast2(h3f[k]);
        ulonglong2 w = *(const ulonglong2*)&((ull*)sW4)[k * 8 + q4 * 2];
        fma2(acc4[0], hh, w.x); fma2(acc4[1], hh, w.y);
    }
    float z0, z1, z2, z3;
    unpack2(acc4[0], z0, z1); unpack2(acc4[1], z2, z3);
    *(float4*)&g_z[(size_t)(i0 + r) * EMB + q4 * 4] = make_float4(z0, z1, z2, z3);

    float ps = z0 * z0 + z1 * z1 + z2 * z2 + z3 * z3;
    ps += __shfl_xor_sync(0xffffffffu, ps, 1);
    ps += __shfl_xor_sync(0xffffffffu, ps, 2);
    if (q4 == 0) g_sq[i0 + r] = ps;
}

// ===========================================================================
// Pairwise inner loop shared pieces: 256 threads, tile 128i x 64j,
// per-thread 8i x 4j. tx = t&15 (j group), ty = t>>4 (i group).
// ===========================================================================

// stage 128 i-rows of z into zasm[8][130] (k2-major ull pairs)
__device__ __forceinline__ void stage_a(ull (*zasm)[130], int i0, int t) {
    const float4* gz4 = (const float4*)g_z;
    #pragma unroll
    for (int rr = 0; rr < 2; rr++) {
        int idx = t + rr * 256;
        int row = idx >> 2, q = idx & 3;
        float4 f = gz4[(size_t)(i0 + row) * 4 + q];
        *(float2*)&zasm[2 * q][row]     = make_float2(f.x, f.y);
        *(float2*)&zasm[2 * q + 1][row] = make_float2(f.z, f.w);
    }
}

// stage 64 j-rows of z into zbsm[8][66] with bank swizzle
__device__ __forceinline__ void stage_b(ull (*zbsm)[66], int j0, int t) {
    const float4* gz4 = (const float4*)g_z;
    int row = t >> 2, q = t & 3;
    float4 f = gz4[(size_t)(j0 + row) * 4 + q];
    int p = bswz(row);
    *(float2*)&zbsm[2 * q][p]     = make_float2(f.x, f.y);
    *(float2*)&zbsm[2 * q + 1][p] = make_float2(f.z, f.w);
}

__device__ __forceinline__ void inner_mma(ull* acc, const ull (*zasm)[130],
                                          const ull (*zbsm)[66], int tx, int ty) {
    #pragma unroll
    for (int k2 = 0; k2 < 8; k2++) {
        const ull* br = zbsm[k2];
        ulonglong2 b01 = *(const ulonglong2*)&br[2 * tx];        // j = 4tx, 4tx+1
        ulonglong2 b23 = *(const ulonglong2*)&br[32 + 2 * tx];   // j = 4tx+2, 4tx+3
        const ull* ar = &zasm[k2][ty * 8];
        ulonglong2 a01 = *(const ulonglong2*)&ar[0];
        ulonglong2 a23 = *(const ulonglong2*)&ar[2];
        ulonglong2 a45 = *(const ulonglong2*)&ar[4];
        ulonglong2 a67 = *(const ulonglong2*)&ar[6];
        ull av[8] = {a01.x, a01.y, a23.x, a23.y, a45.x, a45.y, a67.x, a67.y};
        #pragma unroll
        for (int ii = 0; ii < 8; ii++) {
            fma2(acc[ii * 4 + 0], av[ii], b01.x);
            fma2(acc[ii * 4 + 1], av[ii], b01.y);
            fma2(acc[ii * 4 + 2], av[ii], b23.x);
            fma2(acc[ii * 4 + 3], av[ii], b23.y);
        }
    }
}

// ===========================================================================
// Kernel 2: row sums. grid (8 j-chunks, 64 i-stripes). atomicAdd partials.
// ===========================================================================
__global__ __launch_bounds__(256) void rowsum_kernel()
{
    __shared__ ull zasm[8][130];
    __shared__ ull zbsm[8][66];
    __shared__ float sqis[128];
    __shared__ float sqjs[64];

    const int t = threadIdx.x, tx = t & 15, ty = t >> 4;
    const int i0 = blockIdx.y * 128;
    const int jbase = blockIdx.x * 1024;

    stage_a(zasm, i0, t);
    if (t < 128) sqis[t] = g_sq[i0 + t];

    float rs[8];
    #pragma unroll
    for (int ii = 0; ii < 8; ii++) rs[ii] = 0.0f;

    for (int jt = 0; jt < 16; jt++) {
        const int j0 = jbase + jt * 64;
        __syncthreads();
        stage_b(zbsm, j0, t);
        if (t >= 192) sqjs[t - 192] = g_sq[j0 + (t - 192)];
        __syncthreads();

        ull acc[32];
        #pragma unroll
        for (int m = 0; m < 32; m++) acc[m] = 0ull;
        inner_mma(acc, zasm, zbsm, tx, ty);

        float sj0 = sqjs[tx * 4 + 0], sj1 = sqjs[tx * 4 + 1];
        float sj2 = sqjs[tx * 4 + 2], sj3 = sqjs[tx * 4 + 3];
        #pragma unroll
        for (int ii = 0; ii < 8; ii++) {
            float si = sqis[ty * 8 + ii];
            float lo, hi, dot, dist, p;
            unpack2(acc[ii * 4 + 0], lo, hi); dot = lo + hi;
            dist = fmaxf(fmaf(-2.0f, dot, si + sj0), 0.0f); p = frcp(1.0f + dist);
            unpack2(acc[ii * 4 + 1], lo, hi); dot = lo + hi;
            dist = fmaxf(fmaf(-2.0f, dot, si + sj1), 0.0f); p += frcp(1.0f + dist);
            unpack2(acc[ii * 4 + 2], lo, hi); dot = lo + hi;
            dist = fmaxf(fmaf(-2.0f, dot, si + sj2), 0.0f); p += frcp(1.0f + dist);
            unpack2(acc[ii * 4 + 3], lo, hi); dot = lo + hi;
            dist = fmaxf(fmaf(-2.0f, dot, si + sj3), 0.0f); p += frcp(1.0f + dist);
            rs[ii] += p;
        }
    }

    // reduce over the 16 tx lanes (xor masks stay within the ty half-warp)
    #pragma unroll
    for (int ii = 0; ii < 8; ii++) {
        float v = rs[ii];
        v += __shfl_xor_sync(0xffffffffu, v, 1);
        v += __shfl_xor_sync(0xffffffffu, v, 2);
        v += __shfl_xor_sync(0xffffffffu, v, 4);
        v += __shfl_xor_sync(0xffffffffu, v, 8);
        rs[ii] = v;
    }
    if (tx == 0) {
        #pragma unroll
        for (int ii = 0; ii < 8; ii++)
            atomicAdd(&g_rowsum[i0 + ty * 8 + ii], rs[ii]);
    }
}

// ===========================================================================
// Kernel 3: writer. grid (128 j, 64 i). recompute + normalize + store.
// ===========================================================================
__global__ __launch_bounds__(256) void writer_kernel(float* __restrict__ out)
{
    __shared__ ull zasm[8][130];
    __shared__ ull zbsm[8][66];
    __shared__ float sqis[128];
    __shared__ float sqjs[64];
    __shared__ float rinvs[128];

    const int t = threadIdx.x, tx = t & 15, ty = t >> 4;
    const int i0 = blockIdx.y * 128;
    const int j0 = blockIdx.x * 64;

    stage_a(zasm, i0, t);
    stage_b(zbsm, j0, t);
    if (t < 128) sqis[t] = g_sq[i0 + t];
    else rinvs[t - 128] = frcp(g_rowsum[i0 + (t - 128)]);
    if (t < 64) sqjs[t] = g_sq[j0 + t];
    __syncthreads();

    ull acc[32];
    #pragma unroll
    for (int m = 0; m < 32; m++) acc[m] = 0ull;
    inner_mma(acc, zasm, zbsm, tx, ty);

    const float sj0 = sqjs[tx * 4 + 0], sj1 = sqjs[tx * 4 + 1];
    const float sj2 = sqjs[tx * 4 + 2], sj3 = sqjs[tx * 4 + 3];

    #pragma unroll
    for (int ii = 0; ii < 8; ii++) {
        const int irow = ty * 8 + ii;
        const float si = sqis[irow];
        const float rv = rinvs[irow];
        float lo, hi, dot, dist;
        float4 v;
        unpack2(acc[ii * 4 + 0], lo, hi); dot = lo + hi;
        dist = fmaxf(fmaf(-2.0f, dot, si + sj0), 0.0f); v.x = frcp(1.0f + dist) * rv;
        unpack2(acc[ii * 4 + 1], lo, hi); dot = lo + hi;
        dist = fmaxf(fmaf(-2.0f, dot, si + sj1), 0.0f); v.y = frcp(1.0f + dist) * rv;
        unpack2(acc[ii * 4 + 2], lo, hi); dot = lo + hi;
        dist = fmaxf(fmaf(-2.0f, dot, si + sj2), 0.0f); v.z = frcp(1.0f + dist) * rv;
        unpack2(acc[ii * 4 + 3], lo, hi); dot = lo + hi;
        dist = fmaxf(fmaf(-2.0f, dot, si + sj3), 0.0f); v.w = frcp(1.0f + dist) * rv;

        *(float4*)&out[(size_t)(i0 + irow) * N_PTS + j0 + tx * 4] = v;
    }
}

// ---------------------------------------------------------------------------
extern "C" void kernel_launch(void* const* d_in, const int* in_sizes, int n_in,
                              void* d_out, int out_size)
{
    const float* x  = (const float*)d_in[0];
    const float* W1 = (const float*)d_in[1];
    const float* b1 = (const float*)d_in[2];
    const float* W2 = (const float*)d_in[3];
    const float* b2 = (const float*)d_in[4];
    const float* W3 = (const float*)d_in[5];
    const float* b3 = (const float*)d_in[6];
    const float* W4 = (const float*)d_in[7];
    const float* b4 = (const float*)d_in[8];
    float* out = (float*)d_out;

    cudaFuncSetAttribute(encoder_kernel,
                         cudaFuncAttributeMaxDynamicSharedMemorySize, ENC_SMEM);

    encoder_kernel<<<N_PTS / 64, 256, ENC_SMEM>>>(x, W1, b1, W2, b2, W3, b3, W4, b4);
    rowsum_kernel<<<dim3(8, 64), 256>>>();
    writer_kernel<<<dim3(N_PTS / 64, N_PTS / 128), 256>>>(out);
}

// round 3
// speedup vs baseline: 2.0059x; 1.1793x over previous
#include <cuda_runtime.h>
#include <cuda_bf16.h>
#include <cstdint>

typedef unsigned long long ull;

#define N_PTS 8192
#define DIM   128
#define EMB   16

// Scratch (device globals — no allocation allowed)
__device__ __align__(16) float g_z[N_PTS * EMB];
__device__ float g_sq[N_PTS];
__device__ float g_rowsum[N_PTS];

__device__ __forceinline__ float frcp(float x) {
    float r;
    asm("rcp.approx.ftz.f32 %0, %1;" : "=f"(r) : "f"(x));
    return r;
}
__device__ __forceinline__ void fma2(ull &d, ull a, ull b) {
    asm("fma.rn.f32x2 %0, %1, %2, %0;" : "+l"(d) : "l"(a), "l"(b));
}
__device__ __forceinline__ void unpack2(ull v, float &lo, float &hi) {
    asm("mov.b64 {%0, %1}, %2;" : "=f"(lo), "=f"(hi) : "l"(v));
}
__device__ __forceinline__ ull bcast2(float x) {
    ull v;
    asm("mov.b64 %0, {%1, %1};" : "=l"(v) : "f"(x));
    return v;
}

// b-tile 16B-chunk swizzle for the 256-thread (tx 0..15) inner loop
__device__ __forceinline__ int bswz(int j) {
    return 2 * ((j >> 2) + ((j >> 1) & 1) * 16) + (j & 1);
}

// ===========================================================================
// Encoder: 256 blocks x 256 threads, 32 rows/block.
// Layer 1: thread = (rowpair rg, outquad og): 2 rows x 4 cols -> W1 reuse.
// Layers 2-4: 8 threads/row output-split.
// ===========================================================================
#define OFF_W1   0            // float[128][64]   32768
#define OFF_X    32768        // float[32][132]   16896
#define OFF_W2   49664        // float[64][32]     8192
#define OFF_W3   57856        // float[32][16]     2048
#define OFF_W4   59904        // float[16][16]     1024
#define OFF_B1   60928        // 256
#define OFF_B2   61184        // 128
#define OFF_B3   61312        // 64
#define OFF_B4   61376        // 64
#define OFF_E1   61440        // float[32][68]     8704
#define OFF_E2   70144        // float[32][36]     4608
#define OFF_E3   74752        // float[32][20]     2560
#define ENC_SMEM 77312

__global__ __launch_bounds__(256) void encoder_kernel(
    const float* __restrict__ x,
    const float* __restrict__ W1, const float* __restrict__ b1,
    const float* __restrict__ W2, const float* __restrict__ b2,
    const float* __restrict__ W3, const float* __restrict__ b3,
    const float* __restrict__ W4, const float* __restrict__ b4)
{
    extern __shared__ char dyn[];
    float* sW1 = (float*)(dyn + OFF_W1);
    float* sx  = (float*)(dyn + OFF_X);
    float* sW2 = (float*)(dyn + OFF_W2);
    float* sW3 = (float*)(dyn + OFF_W3);
    float* sW4 = (float*)(dyn + OFF_W4);
    float* sb1 = (float*)(dyn + OFF_B1);
    float* sb2 = (float*)(dyn + OFF_B2);
    float* sb3 = (float*)(dyn + OFF_B3);
    float* sb4 = (float*)(dyn + OFF_B4);
    float* e1  = (float*)(dyn + OFF_E1);
    float* e2  = (float*)(dyn + OFF_E2);
    float* e3  = (float*)(dyn + OFF_E3);

    const int t  = threadIdx.x;
    const int i0 = blockIdx.x * 32;

    // zero rowsum accumulators (consumed by rowsum kernel atomics)
    int gid = blockIdx.x * 256 + t;
    if (gid < N_PTS) g_rowsum[gid] = 0.0f;

    // ---- cooperative staging (coalesced) ----
    {
        const ulonglong2* s = (const ulonglong2*)W1;
        ulonglong2* d = (ulonglong2*)sW1;
        #pragma unroll
        for (int r = 0; r < 8; r++) d[t + r * 256] = s[t + r * 256];
    }
    {
        const float4* x4 = (const float4*)(x + (size_t)i0 * DIM);
        #pragma unroll
        for (int r = 0; r < 4; r++) {
            int idx = t + r * 256;
            int row = idx >> 5, c = idx & 31;
            *(float4*)&sx[row * 132 + c * 4] = x4[idx];
        }
    }
    {
        const float4* s = (const float4*)W2;
        float4* d = (float4*)sW2;
        d[t] = s[t]; d[t + 256] = s[t + 256];
    }
    if (t < 128) ((float4*)sW3)[t] = ((const float4*)W3)[t];
    if (t < 64)  ((float4*)sW4)[t] = ((const float4*)W4)[t];
    if (t < 64) sb1[t] = b1[t];
    if (t < 32) sb2[t] = b2[t];
    if (t < 16) { sb3[t] = b3[t]; sb4[t] = b4[t]; }
    __syncthreads();

    // ---- layer 1: 128 -> 64. thread = 2 rows x 4 out cols ----
    {
        const int og = t & 15, rg = t >> 4;
        const int r0 = rg * 2, r1 = r0 + 1;
        ull a00 = ((const ull*)sb1)[og * 2];
        ull a01 = ((const ull*)sb1)[og * 2 + 1];
        ull a10 = a00, a11 = a01;
        const ull* w1u = (const ull*)sW1;
        #pragma unroll 4
        for (int k4 = 0; k4 < 32; k4++) {
            float4 x0 = *(const float4*)&sx[r0 * 132 + k4 * 4];
            float4 x1 = *(const float4*)&sx[r1 * 132 + k4 * 4];
            float xs0[4] = {x0.x, x0.y, x0.z, x0.w};
            float xs1[4] = {x1.x, x1.y, x1.z, x1.w};
            #pragma unroll
            for (int c = 0; c < 4; c++) {
                ulonglong2 w = *(const ulonglong2*)&w1u[(k4 * 4 + c) * 32 + og * 2];
                ull v0 = bcast2(xs0[c]);
                ull v1 = bcast2(xs1[c]);
                fma2(a00, v0, w.x); fma2(a01, v0, w.y);
                fma2(a10, v1, w.x); fma2(a11, v1, w.y);
            }
        }
        float p, q, r, s;
        unpack2(a00, p, q); unpack2(a01, r, s);
        *(float4*)&e1[r0 * 68 + og * 4] =
            make_float4(fmaxf(p, 0.f), fmaxf(q, 0.f), fmaxf(r, 0.f), fmaxf(s, 0.f));
        unpack2(a10, p, q); unpack2(a11, r, s);
        *(float4*)&e1[r1 * 68 + og * 4] =
            make_float4(fmaxf(p, 0.f), fmaxf(q, 0.f), fmaxf(r, 0.f), fmaxf(s, 0.f));
    }
    __syncthreads();

    const int row = t >> 3;
    const int e   = t & 7;

    // ---- layer 2: 64 -> 32 ; 8 threads/row, 4 outs each ----
    {
        ull c0 = ((const ull*)sb2)[e * 2];
        ull c1 = ((const ull*)sb2)[e * 2 + 1];
        const float* h1r = &e1[row * 68];
        const ull* w2u = (const ull*)sW2;
        #pragma unroll 4
        for (int k4 = 0; k4 < 16; k4++) {
            float4 h = *(const float4*)&h1r[k4 * 4];
            float hs[4] = {h.x, h.y, h.z, h.w};
            #pragma unroll
            for (int c = 0; c < 4; c++) {
                ulonglong2 w = *(const ulonglong2*)&w2u[(k4 * 4 + c) * 16 + e * 2];
                ull hb = bcast2(hs[c]);
                fma2(c0, hb, w.x); fma2(c1, hb, w.y);
            }
        }
        float p, q, r, s;
        unpack2(c0, p, q); unpack2(c1, r, s);
        *(float4*)&e2[row * 36 + e * 4] =
            make_float4(fmaxf(p, 0.f), fmaxf(q, 0.f), fmaxf(r, 0.f), fmaxf(s, 0.f));
    }
    __syncthreads();

    // ---- layer 3: 32 -> 16 ; 2 outs each ----
    {
        ull d0 = ((const ull*)sb3)[e];
        const float* h2r = &e2[row * 36];
        const ull* w3u = (const ull*)sW3;
        #pragma unroll
        for (int k4 = 0; k4 < 8; k4++) {
            float4 h = *(const float4*)&h2r[k4 * 4];
            float hs[4] = {h.x, h.y, h.z, h.w};
            #pragma unroll
            for (int c = 0; c < 4; c++) {
                ull w = w3u[(k4 * 4 + c) * 8 + e];
                fma2(d0, bcast2(hs[c]), w);
            }
        }
        float p, q;
        unpack2(d0, p, q);
        *(float2*)&e3[row * 20 + e * 2] = make_float2(fmaxf(p, 0.f), fmaxf(q, 0.f));
    }
    __syncthreads();

    // ---- layer 4: 16 -> 16 (no relu) ; 2 outs each ----
    {
        ull f0 = ((const ull*)sb4)[e];
        const float* h3r = &e3[row * 20];
        const ull* w4u = (const ull*)sW4;
        #pragma unroll
        for (int k4 = 0; k4 < 4; k4++) {
            float4 h = *(const float4*)&h3r[k4 * 4];
            float hs[4] = {h.x, h.y, h.z, h.w};
            #pragma unroll
            for (int c = 0; c < 4; c++) {
                ull w = w4u[(k4 * 4 + c) * 8 + e];
                fma2(f0, bcast2(hs[c]), w);
            }
        }
        float z0, z1;
        unpack2(f0, z0, z1);
        *(float2*)&g_z[(size_t)(i0 + row) * EMB + e * 2] = make_float2(z0, z1);

        float ps = z0 * z0 + z1 * z1;
        ps += __shfl_xor_sync(0xffffffffu, ps, 1);
        ps += __shfl_xor_sync(0xffffffffu, ps, 2);
        ps += __shfl_xor_sync(0xffffffffu, ps, 4);
        if (e == 0) g_sq[i0 + row] = ps;
    }
}

// ===========================================================================
// 256-thread pairwise pieces (writer): tile 128i x 64j, thread 8i x 4j.
// ===========================================================================
__device__ __forceinline__ void stage_a(ull (*zasm)[130], int i0, int t) {
    const float4* gz4 = (const float4*)g_z;
    #pragma unroll
    for (int rr = 0; rr < 2; rr++) {
        int idx = t + rr * 256;
        int row = idx >> 2, q = idx & 3;
        float4 f = gz4[(size_t)(i0 + row) * 4 + q];
        *(float2*)&zasm[2 * q][row]     = make_float2(f.x, f.y);
        *(float2*)&zasm[2 * q + 1][row] = make_float2(f.z, f.w);
    }
}

__device__ __forceinline__ void inner_mma(ull* acc, const ull (*zasm)[130],
                                          const ull (*zbsm)[66], int tx, int ty) {
    #pragma unroll
    for (int k2 = 0; k2 < 8; k2++) {
        const ull* br = zbsm[k2];
        ulonglong2 b01 = *(const ulonglong2*)&br[2 * tx];
        ulonglong2 b23 = *(const ulonglong2*)&br[32 + 2 * tx];
        const ull* ar = &zasm[k2][ty * 8];
        ulonglong2 a01 = *(const ulonglong2*)&ar[0];
        ulonglong2 a23 = *(const ulonglong2*)&ar[2];
        ulonglong2 a45 = *(const ulonglong2*)&ar[4];
        ulonglong2 a67 = *(const ulonglong2*)&ar[6];
        ull av[8] = {a01.x, a01.y, a23.x, a23.y, a45.x, a45.y, a67.x, a67.y};
        #pragma unroll
        for (int ii = 0; ii < 8; ii++) {
            fma2(acc[ii * 4 + 0], av[ii], b01.x);
            fma2(acc[ii * 4 + 1], av[ii], b01.y);
            fma2(acc[ii * 4 + 2], av[ii], b23.x);
            fma2(acc[ii * 4 + 3], av[ii], b23.y);
        }
    }
}

// ===========================================================================
// Kernel 2: symmetric row sums. grid(64,64), keep bx >= by (upper triangle).
// 512 threads, tile 128i x 128j, thread 8i x 4j (tx 0..31, ty 0..15).
// rowAcc -> rows i ; colAcc (transposed contribution) -> rows j.
// ===========================================================================
__global__ __launch_bounds__(512) void rowsum_kernel()
{
    const int bx = blockIdx.x, by = blockIdx.y;
    if (by > bx) return;

    __shared__ ull zasm[8][132];
    __shared__ ull zbsm[8][132];
    __shared__ float sqis[128];
    __shared__ float sqjs[128];
    __shared__ float rowacc[128];
    __shared__ float colacc[128];

    const int t = threadIdx.x, tx = t & 31, ty = t >> 5;
    const int i0 = by * 128, j0 = bx * 128;
    const float4* gz4 = (const float4*)g_z;
    const bool diag = (bx == by);

    {
        int row = t >> 2, q = t & 3;
        float4 fa = gz4[(size_t)(i0 + row) * 4 + q];
        *(float2*)&zasm[2 * q][row]     = make_float2(fa.x, fa.y);
        *(float2*)&zasm[2 * q + 1][row] = make_float2(fa.z, fa.w);
        float4 fb = gz4[(size_t)(j0 + row) * 4 + q];
        *(float2*)&zbsm[2 * q][row]     = make_float2(fb.x, fb.y);
        *(float2*)&zbsm[2 * q + 1][row] = make_float2(fb.z, fb.w);
    }
    if (t < 128) sqis[t] = g_sq[i0 + t];
    else if (t < 256) sqjs[t - 128] = g_sq[j0 + (t - 128)];
    else if (t < 384) rowacc[t - 256] = 0.0f;
    else colacc[t - 384] = 0.0f;
    __syncthreads();

    ull acc[32];
    #pragma unroll
    for (int m = 0; m < 32; m++) acc[m] = 0ull;

    #pragma unroll
    for (int k2 = 0; k2 < 8; k2++) {
        ulonglong2 b01 = *(const ulonglong2*)&zbsm[k2][4 * tx];
        ulonglong2 b23 = *(const ulonglong2*)&zbsm[k2][4 * tx + 2];
        const ull* ar = &zasm[k2][ty * 8];
        ulonglong2 a01 = *(const ulonglong2*)&ar[0];
        ulonglong2 a23 = *(const ulonglong2*)&ar[2];
        ulonglong2 a45 = *(const ulonglong2*)&ar[4];
        ulonglong2 a67 = *(const ulonglong2*)&ar[6];
        ull av[8] = {a01.x, a01.y, a23.x, a23.y, a45.x, a45.y, a67.x, a67.y};
        #pragma unroll
        for (int ii = 0; ii < 8; ii++) {
            fma2(acc[ii * 4 + 0], av[ii], b01.x);
            fma2(acc[ii * 4 + 1], av[ii], b01.y);
            fma2(acc[ii * 4 + 2], av[ii], b23.x);
            fma2(acc[ii * 4 + 3], av[ii], b23.y);
        }
    }

    const float sj0 = sqjs[tx * 4 + 0], sj1 = sqjs[tx * 4 + 1];
    const float sj2 = sqjs[tx * 4 + 2], sj3 = sqjs[tx * 4 + 3];
    float colp0 = 0.f, colp1 = 0.f, colp2 = 0.f, colp3 = 0.f;

    #pragma unroll
    for (int ii = 0; ii < 8; ii++) {
        const float si = sqis[ty * 8 + ii];
        float lo, hi, dot, dist, n0, n1, n2, n3;
        unpack2(acc[ii * 4 + 0], lo, hi); dot = lo + hi;
        dist = fmaxf(fmaf(-2.0f, dot, si + sj0), 0.0f); n0 = frcp(1.0f + dist);
        unpack2(acc[ii * 4 + 1], lo, hi); dot = lo + hi;
        dist = fmaxf(fmaf(-2.0f, dot, si + sj1), 0.0f); n1 = frcp(1.0f + dist);
        unpack2(acc[ii * 4 + 2], lo, hi); dot = lo + hi;
        dist = fmaxf(fmaf(-2.0f, dot, si + sj2), 0.0f); n2 = frcp(1.0f + dist);
        unpack2(acc[ii * 4 + 3], lo, hi); dot = lo + hi;
        dist = fmaxf(fmaf(-2.0f, dot, si + sj3), 0.0f); n3 = frcp(1.0f + dist);

        float v = (n0 + n1) + (n2 + n3);
        v += __shfl_xor_sync(0xffffffffu, v, 1);
        v += __shfl_xor_sync(0xffffffffu, v, 2);
        v += __shfl_xor_sync(0xffffffffu, v, 4);
        v += __shfl_xor_sync(0xffffffffu, v, 8);
        v += __shfl_xor_sync(0xffffffffu, v, 16);
        if (tx == 0) rowacc[ty * 8 + ii] = v;

        colp0 += n0; colp1 += n1; colp2 += n2; colp3 += n3;
    }

    if (!diag) {
        atomicAdd(&colacc[tx * 4 + 0], colp0);
        atomicAdd(&colacc[tx * 4 + 1], colp1);
        atomicAdd(&colacc[tx * 4 + 2], colp2);
        atomicAdd(&colacc[tx * 4 + 3], colp3);
    }
    __syncthreads();

    if (t < 128) atomicAdd(&g_rowsum[i0 + t], rowacc[t]);
    if (!diag && t >= 128 && t < 256) atomicAdd(&g_rowsum[j0 + (t - 128)], colacc[t - 128]);
}

// ===========================================================================
// Kernel 3: writer. grid(32 jgroups of 256, 64 i-stripes of 128).
// 4 j-tiles per block, double-buffered b staging with global prefetch.
// ===========================================================================
__global__ __launch_bounds__(256) void writer_kernel(float* __restrict__ out)
{
    __shared__ ull zasm[8][130];
    __shared__ ull zbsm[2][8][66];
    __shared__ float sqis[128];
    __shared__ float rinvs[128];
    __shared__ float sqjs[2][64];

    const int t = threadIdx.x, tx = t & 15, ty = t >> 4;
    const int i0 = blockIdx.y * 128;
    const int jbase = blockIdx.x * 256;
    const float4* gz4 = (const float4*)g_z;
    const int prow = t >> 2, pq = t & 3;
    const int pslot = bswz(prow);

    stage_a(zasm, i0, t);
    {
        float4 f = gz4[(size_t)(jbase + prow) * 4 + pq];
        *(float2*)&zbsm[0][2 * pq][pslot]     = make_float2(f.x, f.y);
        *(float2*)&zbsm[0][2 * pq + 1][pslot] = make_float2(f.z, f.w);
    }
    if (t < 128) sqis[t] = g_sq[i0 + t];
    else rinvs[t - 128] = frcp(g_rowsum[i0 + (t - 128)]);
    if (t < 64) sqjs[0][t] = g_sq[jbase + t];
    __syncthreads();

    for (int jt = 0; jt < 4; jt++) {
        const int cur = jt & 1;
        const int j0 = jbase + jt * 64;

        // prefetch next b tile (global loads issued before the fma block)
        float4 pf;
        float psq = 0.0f;
        if (jt < 3) {
            int jn = jbase + (jt + 1) * 64;
            pf = gz4[(size_t)(jn + prow) * 4 + pq];
            if (t < 64) psq = g_sq[jn + t];
        }

        ull acc[32];
        #pragma unroll
        for (int m = 0; m < 32; m++) acc[m] = 0ull;
        inner_mma(acc, zasm, zbsm[cur], tx, ty);

        if (jt < 3) {
            *(float2*)&zbsm[1 - cur][2 * pq][pslot]     = make_float2(pf.x, pf.y);
            *(float2*)&zbsm[1 - cur][2 * pq + 1][pslot] = make_float2(pf.z, pf.w);
            if (t < 64) sqjs[1 - cur][t] = psq;
        }

        const float sj0 = sqjs[cur][tx * 4 + 0], sj1 = sqjs[cur][tx * 4 + 1];
        const float sj2 = sqjs[cur][tx * 4 + 2], sj3 = sqjs[cur][tx * 4 + 3];

        #pragma unroll
        for (int ii = 0; ii < 8; ii++) {
            const int irow = ty * 8 + ii;
            const float si = sqis[irow];
            const float rv = rinvs[irow];
            float lo, hi, dot, dist;
            float4 v;
            unpack2(acc[ii * 4 + 0], lo, hi); dot = lo + hi;
            dist = fmaxf(fmaf(-2.0f, dot, si + sj0), 0.0f); v.x = frcp(1.0f + dist) * rv;
            unpack2(acc[ii * 4 + 1], lo, hi); dot = lo + hi;
            dist = fmaxf(fmaf(-2.0f, dot, si + sj1), 0.0f); v.y = frcp(1.0f + dist) * rv;
            unpack2(acc[ii * 4 + 2], lo, hi); dot = lo + hi;
            dist = fmaxf(fmaf(-2.0f, dot, si + sj2), 0.0f); v.z = frcp(1.0f + dist) * rv;
            unpack2(acc[ii * 4 + 3], lo, hi); dot = lo + hi;
            dist = fmaxf(fmaf(-2.0f, dot, si + sj3), 0.0f); v.w = frcp(1.0f + dist) * rv;

            *(float4*)&out[(size_t)(i0 + irow) * N_PTS + j0 + tx * 4] = v;
        }
        __syncthreads();
    }
}

// ---------------------------------------------------------------------------
extern "C" void kernel_launch(void* const* d_in, const int* in_sizes, int n_in,
                              void* d_out, int out_size)
{
    const float* x  = (const float*)d_in[0];
    const float* W1 = (const float*)d_in[1];
    const float* b1 = (const float*)d_in[2];
    const float* W2 = (const float*)d_in[3];
    const float* b2 = (const float*)d_in[4];
    const float* W3 = (const float*)d_in[5];
    const float* b3 = (const float*)d_in[6];
    const float* W4 = (const float*)d_in[7];
    const float* b4 = (const float*)d_in[8];
    float* out = (float*)d_out;

    cudaFuncSetAttribute(encoder_kernel,
                         cudaFuncAttributeMaxDynamicSharedMemorySize, ENC_SMEM);

    encoder_kernel<<<N_PTS / 32, 256, ENC_SMEM>>>(x, W1, b1, W2, b2, W3, b3, W4, b4);
    rowsum_kernel<<<dim3(64, 64), 512>>>();
    writer_kernel<<<dim3(32, 64), 256>>>(out);
}

// round 4
// speedup vs baseline: 2.2323x; 1.1129x over previous
#include <cuda_runtime.h>
#include <cuda_bf16.h>
#include <cstdint>

typedef unsigned long long ull;

#define N_PTS 8192
#define DIM   128
#define EMB   16

// Scratch (device globals — no allocation allowed)
__device__ __align__(16) float g_z[N_PTS * EMB];
__device__ float g_sq[N_PTS];
__device__ float g_rowsum[N_PTS];

__device__ __forceinline__ float frcp(float x) {
    float r;
    asm("rcp.approx.ftz.f32 %0, %1;" : "=f"(r) : "f"(x));
    return r;
}
__device__ __forceinline__ void fma2(ull &d, ull a, ull b) {
    asm("fma.rn.f32x2 %0, %1, %2, %0;" : "+l"(d) : "l"(a), "l"(b));
}
__device__ __forceinline__ void unpack2(ull v, float &lo, float &hi) {
    asm("mov.b64 {%0, %1}, %2;" : "=f"(lo), "=f"(hi) : "l"(v));
}
__device__ __forceinline__ ull bcast2(float x) {
    ull v;
    asm("mov.b64 %0, {%1, %1};" : "=l"(v) : "f"(x));
    return v;
}

// triangular linear block id -> (row r, col c) with c >= r, 64x64 tile grid
// off(r) = r*(129-r)/2
__device__ __forceinline__ int tri_off(int r) { return (r * (129 - r)) >> 1; }
__device__ __forceinline__ void tri_decode(int b, int &r, int &c) {
    int rr = (int)((129.0f - sqrtf(16641.0f - 8.0f * (float)b)) * 0.5f);
    if (rr < 0) rr = 0;
    if (rr > 63) rr = 63;
    while (rr < 63 && tri_off(rr + 1) <= b) rr++;
    while (rr > 0 && tri_off(rr) > b) rr--;
    r = rr;
    c = rr + (b - tri_off(rr));
}

// ===========================================================================
// Encoder: 256 blocks x 256 threads, 32 rows/block. (unchanged from R3)
// ===========================================================================
#define OFF_W1   0            // float[128][64]   32768
#define OFF_X    32768        // float[32][132]   16896
#define OFF_W2   49664        // float[64][32]     8192
#define OFF_W3   57856        // float[32][16]     2048
#define OFF_W4   59904        // float[16][16]     1024
#define OFF_B1   60928        // 256
#define OFF_B2   61184        // 128
#define OFF_B3   61312        // 64
#define OFF_B4   61376        // 64
#define OFF_E1   61440        // float[32][68]     8704
#define OFF_E2   70144        // float[32][36]     4608
#define OFF_E3   74752        // float[32][20]     2560
#define ENC_SMEM 77312

__global__ __launch_bounds__(256) void encoder_kernel(
    const float* __restrict__ x,
    const float* __restrict__ W1, const float* __restrict__ b1,
    const float* __restrict__ W2, const float* __restrict__ b2,
    const float* __restrict__ W3, const float* __restrict__ b3,
    const float* __restrict__ W4, const float* __restrict__ b4)
{
    extern __shared__ char dyn[];
    float* sW1 = (float*)(dyn + OFF_W1);
    float* sx  = (float*)(dyn + OFF_X);
    float* sW2 = (float*)(dyn + OFF_W2);
    float* sW3 = (float*)(dyn + OFF_W3);
    float* sW4 = (float*)(dyn + OFF_W4);
    float* sb1 = (float*)(dyn + OFF_B1);
    float* sb2 = (float*)(dyn + OFF_B2);
    float* sb3 = (float*)(dyn + OFF_B3);
    float* sb4 = (float*)(dyn + OFF_B4);
    float* e1  = (float*)(dyn + OFF_E1);
    float* e2  = (float*)(dyn + OFF_E2);
    float* e3  = (float*)(dyn + OFF_E3);

    const int t  = threadIdx.x;
    const int i0 = blockIdx.x * 32;

    int gid = blockIdx.x * 256 + t;
    if (gid < N_PTS) g_rowsum[gid] = 0.0f;

    {
        const ulonglong2* s = (const ulonglong2*)W1;
        ulonglong2* d = (ulonglong2*)sW1;
        #pragma unroll
        for (int r = 0; r < 8; r++) d[t + r * 256] = s[t + r * 256];
    }
    {
        const float4* x4 = (const float4*)(x + (size_t)i0 * DIM);
        #pragma unroll
        for (int r = 0; r < 4; r++) {
            int idx = t + r * 256;
            int row = idx >> 5, c = idx & 31;
            *(float4*)&sx[row * 132 + c * 4] = x4[idx];
        }
    }
    {
        const float4* s = (const float4*)W2;
        float4* d = (float4*)sW2;
        d[t] = s[t]; d[t + 256] = s[t + 256];
    }
    if (t < 128) ((float4*)sW3)[t] = ((const float4*)W3)[t];
    if (t < 64)  ((float4*)sW4)[t] = ((const float4*)W4)[t];
    if (t < 64) sb1[t] = b1[t];
    if (t < 32) sb2[t] = b2[t];
    if (t < 16) { sb3[t] = b3[t]; sb4[t] = b4[t]; }
    __syncthreads();

    {
        const int og = t & 15, rg = t >> 4;
        const int r0 = rg * 2, r1 = r0 + 1;
        ull a00 = ((const ull*)sb1)[og * 2];
        ull a01 = ((const ull*)sb1)[og * 2 + 1];
        ull a10 = a00, a11 = a01;
        const ull* w1u = (const ull*)sW1;
        #pragma unroll 4
        for (int k4 = 0; k4 < 32; k4++) {
            float4 x0 = *(const float4*)&sx[r0 * 132 + k4 * 4];
            float4 x1 = *(const float4*)&sx[r1 * 132 + k4 * 4];
            float xs0[4] = {x0.x, x0.y, x0.z, x0.w};
            float xs1[4] = {x1.x, x1.y, x1.z, x1.w};
            #pragma unroll
            for (int c = 0; c < 4; c++) {
                ulonglong2 w = *(const ulonglong2*)&w1u[(k4 * 4 + c) * 32 + og * 2];
                ull v0 = bcast2(xs0[c]);
                ull v1 = bcast2(xs1[c]);
                fma2(a00, v0, w.x); fma2(a01, v0, w.y);
                fma2(a10, v1, w.x); fma2(a11, v1, w.y);
            }
        }
        float p, q, r, s;
        unpack2(a00, p, q); unpack2(a01, r, s);
        *(float4*)&e1[r0 * 68 + og * 4] =
            make_float4(fmaxf(p, 0.f), fmaxf(q, 0.f), fmaxf(r, 0.f), fmaxf(s, 0.f));
        unpack2(a10, p, q); unpack2(a11, r, s);
        *(float4*)&e1[r1 * 68 + og * 4] =
            make_float4(fmaxf(p, 0.f), fmaxf(q, 0.f), fmaxf(r, 0.f), fmaxf(s, 0.f));
    }
    __syncthreads();

    const int row = t >> 3;
    const int e   = t & 7;

    {
        ull c0 = ((const ull*)sb2)[e * 2];
        ull c1 = ((const ull*)sb2)[e * 2 + 1];
        const float* h1r = &e1[row * 68];
        const ull* w2u = (const ull*)sW2;
        #pragma unroll 4
        for (int k4 = 0; k4 < 16; k4++) {
            float4 h = *(const float4*)&h1r[k4 * 4];
            float hs[4] = {h.x, h.y, h.z, h.w};
            #pragma unroll
            for (int c = 0; c < 4; c++) {
                ulonglong2 w = *(const ulonglong2*)&w2u[(k4 * 4 + c) * 16 + e * 2];
                ull hb = bcast2(hs[c]);
                fma2(c0, hb, w.x); fma2(c1, hb, w.y);
            }
        }
        float p, q, r, s;
        unpack2(c0, p, q); unpack2(c1, r, s);
        *(float4*)&e2[row * 36 + e * 4] =
            make_float4(fmaxf(p, 0.f), fmaxf(q, 0.f), fmaxf(r, 0.f), fmaxf(s, 0.f));
    }
    __syncthreads();

    {
        ull d0 = ((const ull*)sb3)[e];
        const float* h2r = &e2[row * 36];
        const ull* w3u = (const ull*)sW3;
        #pragma unroll
        for (int k4 = 0; k4 < 8; k4++) {
            float4 h = *(const float4*)&h2r[k4 * 4];
            float hs[4] = {h.x, h.y, h.z, h.w};
            #pragma unroll
            for (int c = 0; c < 4; c++) {
                ull w = w3u[(k4 * 4 + c) * 8 + e];
                fma2(d0, bcast2(hs[c]), w);
            }
        }
        float p, q;
        unpack2(d0, p, q);
        *(float2*)&e3[row * 20 + e * 2] = make_float2(fmaxf(p, 0.f), fmaxf(q, 0.f));
    }
    __syncthreads();

    {
        ull f0 = ((const ull*)sb4)[e];
        const float* h3r = &e3[row * 20];
        const ull* w4u = (const ull*)sW4;
        #pragma unroll
        for (int k4 = 0; k4 < 4; k4++) {
            float4 h = *(const float4*)&h3r[k4 * 4];
            float hs[4] = {h.x, h.y, h.z, h.w};
            #pragma unroll
            for (int c = 0; c < 4; c++) {
                ull w = w4u[(k4 * 4 + c) * 8 + e];
                fma2(f0, bcast2(hs[c]), w);
            }
        }
        float z0, z1;
        unpack2(f0, z0, z1);
        *(float2*)&g_z[(size_t)(i0 + row) * EMB + e * 2] = make_float2(z0, z1);

        float ps = z0 * z0 + z1 * z1;
        ps += __shfl_xor_sync(0xffffffffu, ps, 1);
        ps += __shfl_xor_sync(0xffffffffu, ps, 2);
        ps += __shfl_xor_sync(0xffffffffu, ps, 4);
        if (e == 0) g_sq[i0 + row] = ps;
    }
}

// ===========================================================================
// Kernel 2: symmetric row sums. 1D triangular grid (2080 blocks), 512 thr.
// tile 128i x 128j, thread 8i x 4j (tx 0..31, ty 0..15).
// ===========================================================================
__global__ __launch_bounds__(512) void rowsum_kernel()
{
    int by, bx;
    tri_decode(blockIdx.x, by, bx);

    __shared__ ull zasm[8][132];
    __shared__ ull zbsm[8][132];
    __shared__ float sqis[128];
    __shared__ float sqjs[128];
    __shared__ float rowacc[128];
    __shared__ float colacc[128];

    const int t = threadIdx.x, tx = t & 31, ty = t >> 5;
    const int i0 = by * 128, j0 = bx * 128;
    const float4* gz4 = (const float4*)g_z;
    const bool diag = (bx == by);

    {
        int row = t >> 2, q = t & 3;
        float4 fa = gz4[(size_t)(i0 + row) * 4 + q];
        *(float2*)&zasm[2 * q][row]     = make_float2(fa.x, fa.y);
        *(float2*)&zasm[2 * q + 1][row] = make_float2(fa.z, fa.w);
        float4 fb = gz4[(size_t)(j0 + row) * 4 + q];
        *(float2*)&zbsm[2 * q][row]     = make_float2(fb.x, fb.y);
        *(float2*)&zbsm[2 * q + 1][row] = make_float2(fb.z, fb.w);
    }
    if (t < 128) sqis[t] = g_sq[i0 + t];
    else if (t < 256) sqjs[t - 128] = g_sq[j0 + (t - 128)];
    else if (t < 384) rowacc[t - 256] = 0.0f;
    else colacc[t - 384] = 0.0f;
    __syncthreads();

    ull acc[32];
    #pragma unroll
    for (int m = 0; m < 32; m++) acc[m] = 0ull;

    #pragma unroll
    for (int k2 = 0; k2 < 8; k2++) {
        ull b[4];
        #pragma unroll
        for (int c = 0; c < 4; c++) b[c] = zbsm[k2][tx + 32 * c];
        const ull* ar = &zasm[k2][ty * 8];
        ulonglong2 a01 = *(const ulonglong2*)&ar[0];
        ulonglong2 a23 = *(const ulonglong2*)&ar[2];
        ulonglong2 a45 = *(const ulonglong2*)&ar[4];
        ulonglong2 a67 = *(const ulonglong2*)&ar[6];
        ull av[8] = {a01.x, a01.y, a23.x, a23.y, a45.x, a45.y, a67.x, a67.y};
        #pragma unroll
        for (int ii = 0; ii < 8; ii++) {
            fma2(acc[ii * 4 + 0], av[ii], b[0]);
            fma2(acc[ii * 4 + 1], av[ii], b[1]);
            fma2(acc[ii * 4 + 2], av[ii], b[2]);
            fma2(acc[ii * 4 + 3], av[ii], b[3]);
        }
    }

    const float sj0 = sqjs[tx];
    const float sj1 = sqjs[tx + 32];
    const float sj2 = sqjs[tx + 64];
    const float sj3 = sqjs[tx + 96];
    float colp0 = 0.f, colp1 = 0.f, colp2 = 0.f, colp3 = 0.f;

    #pragma unroll
    for (int ii = 0; ii < 8; ii++) {
        const float si = sqis[ty * 8 + ii];
        float lo, hi, dot, dist, n0, n1, n2, n3;
        unpack2(acc[ii * 4 + 0], lo, hi); dot = lo + hi;
        dist = fmaxf(fmaf(-2.0f, dot, si + sj0), 0.0f); n0 = frcp(1.0f + dist);
        unpack2(acc[ii * 4 + 1], lo, hi); dot = lo + hi;
        dist = fmaxf(fmaf(-2.0f, dot, si + sj1), 0.0f); n1 = frcp(1.0f + dist);
        unpack2(acc[ii * 4 + 2], lo, hi); dot = lo + hi;
        dist = fmaxf(fmaf(-2.0f, dot, si + sj2), 0.0f); n2 = frcp(1.0f + dist);
        unpack2(acc[ii * 4 + 3], lo, hi); dot = lo + hi;
        dist = fmaxf(fmaf(-2.0f, dot, si + sj3), 0.0f); n3 = frcp(1.0f + dist);

        float v = (n0 + n1) + (n2 + n3);
        v += __shfl_xor_sync(0xffffffffu, v, 1);
        v += __shfl_xor_sync(0xffffffffu, v, 2);
        v += __shfl_xor_sync(0xffffffffu, v, 4);
        v += __shfl_xor_sync(0xffffffffu, v, 8);
        v += __shfl_xor_sync(0xffffffffu, v, 16);
        if (tx == 0) rowacc[ty * 8 + ii] = v;

        colp0 += n0; colp1 += n1; colp2 += n2; colp3 += n3;
    }

    if (!diag) {
        atomicAdd(&colacc[tx],      colp0);
        atomicAdd(&colacc[tx + 32], colp1);
        atomicAdd(&colacc[tx + 64], colp2);
        atomicAdd(&colacc[tx + 96], colp3);
    }
    __syncthreads();

    if (t < 128) atomicAdd(&g_rowsum[i0 + t], rowacc[t]);
    if (!diag && t >= 128 && t < 256) atomicAdd(&g_rowsum[j0 + (t - 128)], colacc[t - 128]);
}

// ===========================================================================
// Kernel 3: symmetric writer. 1D triangular grid (2080 blocks), 512 thr.
// Computes 128x128 numerators once; writes normal tile + transposed tile.
// Thread owns j = tx + 32c -> conflict-free snum STS / transposed LDS.
// ===========================================================================
#define WOFF_ZA   0         // ull[8][132]            8448
#define WOFF_ZB   8448      // ull[8][132]            8448
#define WOFF_SNUM 16896     // float[128][133]       68096
#define WOFF_SQI  84992     // float[128]              512
#define WOFF_SQJ  85504
#define WOFF_RVI  86016
#define WOFF_RVJ  86528
#define WR_SMEM   87040

__global__ __launch_bounds__(512, 1) void writer_kernel(float* __restrict__ out)
{
    extern __shared__ char dyn[];
    ull  (*zasm)[132] = (ull (*)[132])(dyn + WOFF_ZA);
    ull  (*zbsm)[132] = (ull (*)[132])(dyn + WOFF_ZB);
    float* snum  = (float*)(dyn + WOFF_SNUM);
    float* sqis  = (float*)(dyn + WOFF_SQI);
    float* sqjs  = (float*)(dyn + WOFF_SQJ);
    float* rinvi = (float*)(dyn + WOFF_RVI);
    float* rinvj = (float*)(dyn + WOFF_RVJ);

    int by, bx;
    tri_decode(blockIdx.x, by, bx);

    const int t = threadIdx.x, tx = t & 31, ty = t >> 5;
    const int i0 = by * 128, j0 = bx * 128;
    const float4* gz4 = (const float4*)g_z;
    const bool diag = (bx == by);

    {
        int row = t >> 2, q = t & 3;
        float4 fa = gz4[(size_t)(i0 + row) * 4 + q];
        *(float2*)&zasm[2 * q][row]     = make_float2(fa.x, fa.y);
        *(float2*)&zasm[2 * q + 1][row] = make_float2(fa.z, fa.w);
        float4 fb = gz4[(size_t)(j0 + row) * 4 + q];
        *(float2*)&zbsm[2 * q][row]     = make_float2(fb.x, fb.y);
        *(float2*)&zbsm[2 * q + 1][row] = make_float2(fb.z, fb.w);
    }
    if (t < 128) sqis[t] = g_sq[i0 + t];
    else if (t < 256) sqjs[t - 128] = g_sq[j0 + (t - 128)];
    else if (t < 384) rinvi[t - 256] = frcp(g_rowsum[i0 + (t - 256)]);
    else rinvj[t - 384] = frcp(g_rowsum[j0 + (t - 384)]);
    __syncthreads();

    ull acc[32];
    #pragma unroll
    for (int m = 0; m < 32; m++) acc[m] = 0ull;

    #pragma unroll
    for (int k2 = 0; k2 < 8; k2++) {
        ull b[4];
        #pragma unroll
        for (int c = 0; c < 4; c++) b[c] = zbsm[k2][tx + 32 * c];
        const ull* ar = &zasm[k2][ty * 8];
        ulonglong2 a01 = *(const ulonglong2*)&ar[0];
        ulonglong2 a23 = *(const ulonglong2*)&ar[2];
        ulonglong2 a45 = *(const ulonglong2*)&ar[4];
        ulonglong2 a67 = *(const ulonglong2*)&ar[6];
        ull av[8] = {a01.x, a01.y, a23.x, a23.y, a45.x, a45.y, a67.x, a67.y};
        #pragma unroll
        for (int ii = 0; ii < 8; ii++) {
            fma2(acc[ii * 4 + 0], av[ii], b[0]);
            fma2(acc[ii * 4 + 1], av[ii], b[1]);
            fma2(acc[ii * 4 + 2], av[ii], b[2]);
            fma2(acc[ii * 4 + 3], av[ii], b[3]);
        }
    }

    const float sj0 = sqjs[tx];
    const float sj1 = sqjs[tx + 32];
    const float sj2 = sqjs[tx + 64];
    const float sj3 = sqjs[tx + 96];

    #pragma unroll
    for (int ii = 0; ii < 8; ii++) {
        const int irow = ty * 8 + ii;
        const float si = sqis[irow];
        const float rvi = rinvi[irow];
        float* orow = &out[(size_t)(i0 + irow) * N_PTS + j0];
        float* srow = &snum[irow * 133];
        float lo, hi, dot, dist, num;

        unpack2(acc[ii * 4 + 0], lo, hi); dot = lo + hi;
        dist = fmaxf(fmaf(-2.0f, dot, si + sj0), 0.0f); num = frcp(1.0f + dist);
        srow[tx] = num;        orow[tx] = num * rvi;
        unpack2(acc[ii * 4 + 1], lo, hi); dot = lo + hi;
        dist = fmaxf(fmaf(-2.0f, dot, si + sj1), 0.0f); num = frcp(1.0f + dist);
        srow[tx + 32] = num;   orow[tx + 32] = num * rvi;
        unpack2(acc[ii * 4 + 2], lo, hi); dot = lo + hi;
        dist = fmaxf(fmaf(-2.0f, dot, si + sj2), 0.0f); num = frcp(1.0f + dist);
        srow[tx + 64] = num;   orow[tx + 64] = num * rvi;
        unpack2(acc[ii * 4 + 3], lo, hi); dot = lo + hi;
        dist = fmaxf(fmaf(-2.0f, dot, si + sj3), 0.0f); num = frcp(1.0f + dist);
        srow[tx + 96] = num;   orow[tx + 96] = num * rvi;
    }

    if (!diag) {
        __syncthreads();
        #pragma unroll
        for (int ii = 0; ii < 8; ii++) {
            const int jrow = ty * 8 + ii;
            const float rvj = rinvj[jrow];
            float* orow = &out[(size_t)(j0 + jrow) * N_PTS + i0];
            orow[tx]      = snum[(tx)       * 133 + jrow] * rvj;
            orow[tx + 32] = snum[(tx + 32)  * 133 + jrow] * rvj;
            orow[tx + 64] = snum[(tx + 64)  * 133 + jrow] * rvj;
            orow[tx + 96] = snum[(tx + 96)  * 133 + jrow] * rvj;
        }
    }
}

// ---------------------------------------------------------------------------
extern "C" void kernel_launch(void* const* d_in, const int* in_sizes, int n_in,
                              void* d_out, int out_size)
{
    const float* x  = (const float*)d_in[0];
    const float* W1 = (const float*)d_in[1];
    const float* b1 = (const float*)d_in[2];
    const float* W2 = (const float*)d_in[3];
    const float* b2 = (const float*)d_in[4];
    const float* W3 = (const float*)d_in[5];
    const float* b3 = (const float*)d_in[6];
    const float* W4 = (const float*)d_in[7];
    const float* b4 = (const float*)d_in[8];
    float* out = (float*)d_out;

    cudaFuncSetAttribute(encoder_kernel,
                         cudaFuncAttributeMaxDynamicSharedMemorySize, ENC_SMEM);
    cudaFuncSetAttribute(writer_kernel,
                         cudaFuncAttributeMaxDynamicSharedMemorySize, WR_SMEM);

    const int n_tri = (64 * 65) / 2;  // 2080

    encoder_kernel<<<N_PTS / 32, 256, ENC_SMEM>>>(x, W1, b1, W2, b2, W3, b3, W4, b4);
    rowsum_kernel<<<n_tri, 512>>>();
    writer_kernel<<<n_tri, 512, WR_SMEM>>>(out);
}

// round 5
// speedup vs baseline: 2.5608x; 1.1471x over previous
#include <cuda_runtime.h>
#include <cuda_bf16.h>
#include <cstdint>

typedef unsigned long long ull;

#define N_PTS 8192
#define DIM   128
#define EMB   16

// Scratch (device globals — no allocation allowed)
__device__ __align__(16) float g_z[N_PTS * EMB];
__device__ float g_sq[N_PTS];
__device__ float g_rowsum[N_PTS];

__device__ __forceinline__ float frcp(float x) {
    float r;
    asm("rcp.approx.ftz.f32 %0, %1;" : "=f"(r) : "f"(x));
    return r;
}
__device__ __forceinline__ void fma2(ull &d, ull a, ull b) {
    asm("fma.rn.f32x2 %0, %1, %2, %0;" : "+l"(d) : "l"(a), "l"(b));
}
__device__ __forceinline__ void unpack2(ull v, float &lo, float &hi) {
    asm("mov.b64 {%0, %1}, %2;" : "=f"(lo), "=f"(hi) : "l"(v));
}
__device__ __forceinline__ ull bcast2(float x) {
    ull v;
    asm("mov.b64 %0, {%1, %1};" : "=l"(v) : "f"(x));
    return v;
}

// triangular linear block id -> (row r, col c) with c >= r, 128x128 tile grid
// off(r) = r*(257-r)/2 ; total 8256
__device__ __forceinline__ int tri_off128(int r) { return (r * (257 - r)) >> 1; }
__device__ __forceinline__ void tri_decode128(int b, int &r, int &c) {
    int rr = (int)((257.0f - sqrtf(66049.0f - 8.0f * (float)b)) * 0.5f);
    if (rr < 0) rr = 0;
    if (rr > 127) rr = 127;
    while (rr < 127 && tri_off128(rr + 1) <= b) rr++;
    while (rr > 0 && tri_off128(rr) > b) rr--;
    r = rr;
    c = rr + (b - tri_off128(rr));
}

// ===========================================================================
// Encoder: 256 blocks x 256 threads, 32 rows/block. (unchanged)
// ===========================================================================
#define OFF_W1   0            // float[128][64]   32768
#define OFF_X    32768        // float[32][132]   16896
#define OFF_W2   49664        // float[64][32]     8192
#define OFF_W3   57856        // float[32][16]     2048
#define OFF_W4   59904        // float[16][16]     1024
#define OFF_B1   60928        // 256
#define OFF_B2   61184        // 128
#define OFF_B3   61312        // 64
#define OFF_B4   61376        // 64
#define OFF_E1   61440        // float[32][68]     8704
#define OFF_E2   70144        // float[32][36]     4608
#define OFF_E3   74752        // float[32][20]     2560
#define ENC_SMEM 77312

__global__ __launch_bounds__(256) void encoder_kernel(
    const float* __restrict__ x,
    const float* __restrict__ W1, const float* __restrict__ b1,
    const float* __restrict__ W2, const float* __restrict__ b2,
    const float* __restrict__ W3, const float* __restrict__ b3,
    const float* __restrict__ W4, const float* __restrict__ b4)
{
    extern __shared__ char dyn[];
    float* sW1 = (float*)(dyn + OFF_W1);
    float* sx  = (float*)(dyn + OFF_X);
    float* sW2 = (float*)(dyn + OFF_W2);
    float* sW3 = (float*)(dyn + OFF_W3);
    float* sW4 = (float*)(dyn + OFF_W4);
    float* sb1 = (float*)(dyn + OFF_B1);
    float* sb2 = (float*)(dyn + OFF_B2);
    float* sb3 = (float*)(dyn + OFF_B3);
    float* sb4 = (float*)(dyn + OFF_B4);
    float* e1  = (float*)(dyn + OFF_E1);
    float* e2  = (float*)(dyn + OFF_E2);
    float* e3  = (float*)(dyn + OFF_E3);

    const int t  = threadIdx.x;
    const int i0 = blockIdx.x * 32;

    int gid = blockIdx.x * 256 + t;
    if (gid < N_PTS) g_rowsum[gid] = 0.0f;

    {
        const ulonglong2* s = (const ulonglong2*)W1;
        ulonglong2* d = (ulonglong2*)sW1;
        #pragma unroll
        for (int r = 0; r < 8; r++) d[t + r * 256] = s[t + r * 256];
    }
    {
        const float4* x4 = (const float4*)(x + (size_t)i0 * DIM);
        #pragma unroll
        for (int r = 0; r < 4; r++) {
            int idx = t + r * 256;
            int row = idx >> 5, c = idx & 31;
            *(float4*)&sx[row * 132 + c * 4] = x4[idx];
        }
    }
    {
        const float4* s = (const float4*)W2;
        float4* d = (float4*)sW2;
        d[t] = s[t]; d[t + 256] = s[t + 256];
    }
    if (t < 128) ((float4*)sW3)[t] = ((const float4*)W3)[t];
    if (t < 64)  ((float4*)sW4)[t] = ((const float4*)W4)[t];
    if (t < 64) sb1[t] = b1[t];
    if (t < 32) sb2[t] = b2[t];
    if (t < 16) { sb3[t] = b3[t]; sb4[t] = b4[t]; }
    __syncthreads();

    {
        const int og = t & 15, rg = t >> 4;
        const int r0 = rg * 2, r1 = r0 + 1;
        ull a00 = ((const ull*)sb1)[og * 2];
        ull a01 = ((const ull*)sb1)[og * 2 + 1];
        ull a10 = a00, a11 = a01;
        const ull* w1u = (const ull*)sW1;
        #pragma unroll 4
        for (int k4 = 0; k4 < 32; k4++) {
            float4 x0 = *(const float4*)&sx[r0 * 132 + k4 * 4];
            float4 x1 = *(const float4*)&sx[r1 * 132 + k4 * 4];
            float xs0[4] = {x0.x, x0.y, x0.z, x0.w};
            float xs1[4] = {x1.x, x1.y, x1.z, x1.w};
            #pragma unroll
            for (int c = 0; c < 4; c++) {
                ulonglong2 w = *(const ulonglong2*)&w1u[(k4 * 4 + c) * 32 + og * 2];
                ull v0 = bcast2(xs0[c]);
                ull v1 = bcast2(xs1[c]);
                fma2(a00, v0, w.x); fma2(a01, v0, w.y);
                fma2(a10, v1, w.x); fma2(a11, v1, w.y);
            }
        }
        float p, q, r, s;
        unpack2(a00, p, q); unpack2(a01, r, s);
        *(float4*)&e1[r0 * 68 + og * 4] =
            make_float4(fmaxf(p, 0.f), fmaxf(q, 0.f), fmaxf(r, 0.f), fmaxf(s, 0.f));
        unpack2(a10, p, q); unpack2(a11, r, s);
        *(float4*)&e1[r1 * 68 + og * 4] =
            make_float4(fmaxf(p, 0.f), fmaxf(q, 0.f), fmaxf(r, 0.f), fmaxf(s, 0.f));
    }
    __syncthreads();

    const int row = t >> 3;
    const int e   = t & 7;

    {
        ull c0 = ((const ull*)sb2)[e * 2];
        ull c1 = ((const ull*)sb2)[e * 2 + 1];
        const float* h1r = &e1[row * 68];
        const ull* w2u = (const ull*)sW2;
        #pragma unroll 4
        for (int k4 = 0; k4 < 16; k4++) {
            float4 h = *(const float4*)&h1r[k4 * 4];
            float hs[4] = {h.x, h.y, h.z, h.w};
            #pragma unroll
            for (int c = 0; c < 4; c++) {
                ulonglong2 w = *(const ulonglong2*)&w2u[(k4 * 4 + c) * 16 + e * 2];
                ull hb = bcast2(hs[c]);
                fma2(c0, hb, w.x); fma2(c1, hb, w.y);
            }
        }
        float p, q, r, s;
        unpack2(c0, p, q); unpack2(c1, r, s);
        *(float4*)&e2[row * 36 + e * 4] =
            make_float4(fmaxf(p, 0.f), fmaxf(q, 0.f), fmaxf(r, 0.f), fmaxf(s, 0.f));
    }
    __syncthreads();

    {
        ull d0 = ((const ull*)sb3)[e];
        const float* h2r = &e2[row * 36];
        const ull* w3u = (const ull*)sW3;
        #pragma unroll
        for (int k4 = 0; k4 < 8; k4++) {
            float4 h = *(const float4*)&h2r[k4 * 4];
            float hs[4] = {h.x, h.y, h.z, h.w};
            #pragma unroll
            for (int c = 0; c < 4; c++) {
                ull w = w3u[(k4 * 4 + c) * 8 + e];
                fma2(d0, bcast2(hs[c]), w);
            }
        }
        float p, q;
        unpack2(d0, p, q);
        *(float2*)&e3[row * 20 + e * 2] = make_float2(fmaxf(p, 0.f), fmaxf(q, 0.f));
    }
    __syncthreads();

    {
        ull f0 = ((const ull*)sb4)[e];
        const float* h3r = &e3[row * 20];
        const ull* w4u = (const ull*)sW4;
        #pragma unroll
        for (int k4 = 0; k4 < 4; k4++) {
            float4 h = *(const float4*)&h3r[k4 * 4];
            float hs[4] = {h.x, h.y, h.z, h.w};
            #pragma unroll
            for (int c = 0; c < 4; c++) {
                ull w = w4u[(k4 * 4 + c) * 8 + e];
                fma2(f0, bcast2(hs[c]), w);
            }
        }
        float z0, z1;
        unpack2(f0, z0, z1);
        *(float2*)&g_z[(size_t)(i0 + row) * EMB + e * 2] = make_float2(z0, z1);

        float ps = z0 * z0 + z1 * z1;
        ps += __shfl_xor_sync(0xffffffffu, ps, 1);
        ps += __shfl_xor_sync(0xffffffffu, ps, 2);
        ps += __shfl_xor_sync(0xffffffffu, ps, 4);
        if (e == 0) g_sq[i0 + row] = ps;
    }
}

// ===========================================================================
// Shared staging for 64-row tiles: zsm[8][66] (k2-major ull pairs)
// ===========================================================================
__device__ __forceinline__ void stage64(ull (*zsm)[66], int r0, int t) {
    const float4* gz4 = (const float4*)g_z;
    int row = t >> 2, q = t & 3;
    float4 f = gz4[(size_t)(r0 + row) * 4 + q];
    *(float2*)&zsm[2 * q][row]     = make_float2(f.x, f.y);
    *(float2*)&zsm[2 * q + 1][row] = make_float2(f.z, f.w);
}

// inner 4i x 4j mma: acc[16], b at tx+16c, a at ty*4..
__device__ __forceinline__ void mma44(ull* acc, const ull (*zasm)[66],
                                      const ull (*zbsm)[66], int tx, int ty) {
    #pragma unroll
    for (int k2 = 0; k2 < 8; k2++) {
        ull b0 = zbsm[k2][tx];
        ull b1 = zbsm[k2][tx + 16];
        ull b2 = zbsm[k2][tx + 32];
        ull b3 = zbsm[k2][tx + 48];
        ulonglong2 a01 = *(const ulonglong2*)&zasm[k2][ty * 4];
        ulonglong2 a23 = *(const ulonglong2*)&zasm[k2][ty * 4 + 2];
        ull av[4] = {a01.x, a01.y, a23.x, a23.y};
        #pragma unroll
        for (int ii = 0; ii < 4; ii++) {
            fma2(acc[ii * 4 + 0], av[ii], b0);
            fma2(acc[ii * 4 + 1], av[ii], b1);
            fma2(acc[ii * 4 + 2], av[ii], b2);
            fma2(acc[ii * 4 + 3], av[ii], b3);
        }
    }
}

// ===========================================================================
// Kernel 2: symmetric row sums. triangular grid over 64x64 tiles (8256 blk),
// 256 threads, thread 4i x 4j (tx 0..15 -> j=tx+16c, ty 0..15 -> i=4ty+ii).
// ===========================================================================
__global__ __launch_bounds__(256) void rowsum_kernel()
{
    int by, bx;
    tri_decode128(blockIdx.x, by, bx);

    __shared__ ull zasm[8][66];
    __shared__ ull zbsm[8][66];
    __shared__ float sqis[64];
    __shared__ float sqjs[64];
    __shared__ float rowacc[64];
    __shared__ float colacc[64];

    const int t = threadIdx.x, tx = t & 15, ty = t >> 4;
    const int i0 = by * 64, j0 = bx * 64;
    const bool diag = (bx == by);

    stage64(zasm, i0, t);
    stage64(zbsm, j0, t);
    if (t < 64) sqis[t] = g_sq[i0 + t];
    else if (t < 128) sqjs[t - 64] = g_sq[j0 + (t - 64)];
    else if (t < 192) colacc[t - 128] = 0.0f;
    __syncthreads();

    ull acc[16];
    #pragma unroll
    for (int m = 0; m < 16; m++) acc[m] = 0ull;
    mma44(acc, zasm, zbsm, tx, ty);

    const float sj0 = sqjs[tx];
    const float sj1 = sqjs[tx + 16];
    const float sj2 = sqjs[tx + 32];
    const float sj3 = sqjs[tx + 48];
    float colp0 = 0.f, colp1 = 0.f, colp2 = 0.f, colp3 = 0.f;

    #pragma unroll
    for (int ii = 0; ii < 4; ii++) {
        const float si = sqis[ty * 4 + ii];
        float lo, hi, dot, dist, n0, n1, n2, n3;
        unpack2(acc[ii * 4 + 0], lo, hi); dot = lo + hi;
        dist = fmaxf(fmaf(-2.0f, dot, si + sj0), 0.0f); n0 = frcp(1.0f + dist);
        unpack2(acc[ii * 4 + 1], lo, hi); dot = lo + hi;
        dist = fmaxf(fmaf(-2.0f, dot, si + sj1), 0.0f); n1 = frcp(1.0f + dist);
        unpack2(acc[ii * 4 + 2], lo, hi); dot = lo + hi;
        dist = fmaxf(fmaf(-2.0f, dot, si + sj2), 0.0f); n2 = frcp(1.0f + dist);
        unpack2(acc[ii * 4 + 3], lo, hi); dot = lo + hi;
        dist = fmaxf(fmaf(-2.0f, dot, si + sj3), 0.0f); n3 = frcp(1.0f + dist);

        float v = (n0 + n1) + (n2 + n3);
        v += __shfl_xor_sync(0xffffffffu, v, 1);
        v += __shfl_xor_sync(0xffffffffu, v, 2);
        v += __shfl_xor_sync(0xffffffffu, v, 4);
        v += __shfl_xor_sync(0xffffffffu, v, 8);
        if (tx == 0) rowacc[ty * 4 + ii] = v;

        colp0 += n0; colp1 += n1; colp2 += n2; colp3 += n3;
    }

    if (!diag) {
        // sum the two ty-halves of the warp, then shared atomics from lanes 0..15
        colp0 += __shfl_xor_sync(0xffffffffu, colp0, 16);
        colp1 += __shfl_xor_sync(0xffffffffu, colp1, 16);
        colp2 += __shfl_xor_sync(0xffffffffu, colp2, 16);
        colp3 += __shfl_xor_sync(0xffffffffu, colp3, 16);
        if ((t & 16) == 0) {
            atomicAdd(&colacc[tx],      colp0);
            atomicAdd(&colacc[tx + 16], colp1);
            atomicAdd(&colacc[tx + 32], colp2);
            atomicAdd(&colacc[tx + 48], colp3);
        }
    }
    __syncthreads();

    if (t < 64) atomicAdd(&g_rowsum[i0 + t], rowacc[t]);
    if (!diag && t >= 64 && t < 128) atomicAdd(&g_rowsum[j0 + (t - 64)], colacc[t - 64]);
}

// ===========================================================================
// Kernel 3: symmetric writer. triangular grid (8256 blocks), 256 threads.
// Computes 64x64 numerators once; writes normal + transposed tiles.
// snum stride 68 -> conflict-free STS (banks 4*irow + tx + 16c all distinct).
// ===========================================================================
__global__ __launch_bounds__(256) void writer_kernel(float* __restrict__ out)
{
    int by, bx;
    tri_decode128(blockIdx.x, by, bx);

    __shared__ ull zasm[8][66];
    __shared__ ull zbsm[8][66];
    __shared__ float snum[64 * 68];
    __shared__ float sqis[64];
    __shared__ float sqjs[64];
    __shared__ float rinvi[64];
    __shared__ float rinvj[64];

    const int t = threadIdx.x, tx = t & 15, ty = t >> 4;
    const int i0 = by * 64, j0 = bx * 64;
    const bool diag = (bx == by);

    stage64(zasm, i0, t);
    stage64(zbsm, j0, t);
    if (t < 64) sqis[t] = g_sq[i0 + t];
    else if (t < 128) sqjs[t - 64] = g_sq[j0 + (t - 64)];
    else if (t < 192) rinvi[t - 128] = frcp(g_rowsum[i0 + (t - 128)]);
    else rinvj[t - 192] = frcp(g_rowsum[j0 + (t - 192)]);
    __syncthreads();

    ull acc[16];
    #pragma unroll
    for (int m = 0; m < 16; m++) acc[m] = 0ull;
    mma44(acc, zasm, zbsm, tx, ty);

    const float sj0 = sqjs[tx];
    const float sj1 = sqjs[tx + 16];
    const float sj2 = sqjs[tx + 32];
    const float sj3 = sqjs[tx + 48];

    #pragma unroll
    for (int ii = 0; ii < 4; ii++) {
        const int irow = ty * 4 + ii;
        const float si = sqis[irow];
        const float rvi = rinvi[irow];
        float* orow = &out[(size_t)(i0 + irow) * N_PTS + j0];
        float* srow = &snum[irow * 68];
        float lo, hi, dot, dist, num;

        unpack2(acc[ii * 4 + 0], lo, hi); dot = lo + hi;
        dist = fmaxf(fmaf(-2.0f, dot, si + sj0), 0.0f); num = frcp(1.0f + dist);
        srow[tx] = num;       orow[tx] = num * rvi;
        unpack2(acc[ii * 4 + 1], lo, hi); dot = lo + hi;
        dist = fmaxf(fmaf(-2.0f, dot, si + sj1), 0.0f); num = frcp(1.0f + dist);
        srow[tx + 16] = num;  orow[tx + 16] = num * rvi;
        unpack2(acc[ii * 4 + 2], lo, hi); dot = lo + hi;
        dist = fmaxf(fmaf(-2.0f, dot, si + sj2), 0.0f); num = frcp(1.0f + dist);
        srow[tx + 32] = num;  orow[tx + 32] = num * rvi;
        unpack2(acc[ii * 4 + 3], lo, hi); dot = lo + hi;
        dist = fmaxf(fmaf(-2.0f, dot, si + sj3), 0.0f); num = frcp(1.0f + dist);
        srow[tx + 48] = num;  orow[tx + 48] = num * rvi;
    }

    if (!diag) {
        __syncthreads();
        #pragma unroll
        for (int ii = 0; ii < 4; ii++) {
            const int jrow = ty * 4 + ii;
            const float rvj = rinvj[jrow];
            float* orow = &out[(size_t)(j0 + jrow) * N_PTS + i0];
            orow[tx]      = snum[(tx)      * 68 + jrow] * rvj;
            orow[tx + 16] = snum[(tx + 16) * 68 + jrow] * rvj;
            orow[tx + 32] = snum[(tx + 32) * 68 + jrow] * rvj;
            orow[tx + 48] = snum[(tx + 48) * 68 + jrow] * rvj;
        }
    }
}

// ---------------------------------------------------------------------------
extern "C" void kernel_launch(void* const* d_in, const int* in_sizes, int n_in,
                              void* d_out, int out_size)
{
    const float* x  = (const float*)d_in[0];
    const float* W1 = (const float*)d_in[1];
    const float* b1 = (const float*)d_in[2];
    const float* W2 = (const float*)d_in[3];
    const float* b2 = (const float*)d_in[4];
    const float* W3 = (const float*)d_in[5];
    const float* b3 = (const float*)d_in[6];
    const float* W4 = (const float*)d_in[7];
    const float* b4 = (const float*)d_in[8];
    float* out = (float*)d_out;

    cudaFuncSetAttribute(encoder_kernel,
                         cudaFuncAttributeMaxDynamicSharedMemorySize, ENC_SMEM);

    const int n_tri = (128 * 129) / 2;  // 8256

    encoder_kernel<<<N_PTS / 32, 256, ENC_SMEM>>>(x, W1, b1, W2, b2, W3, b3, W4, b4);
    rowsum_kernel<<<n_tri, 256>>>();
    writer_kernel<<<n_tri, 256>>>(out);
}